// round 1
// baseline (speedup 1.0000x reference)
#include <cuda_runtime.h>
#include <cuda_bf16.h>
#include <cstdint>

#define BROWS 32768
#define CDIM  1024
#define CHDIM 256

// ---------------- scratch (device globals; no allocations allowed) ----------------
__device__ __nv_bfloat16 g_t[(size_t)BROWS * CDIM];     // LN output, bf16
__device__ __nv_bfloat16 g_hbuf[(size_t)BROWS * CHDIM]; // GLU output
__device__ __nv_bfloat16 g_gbuf[(size_t)BROWS * CHDIM]; // gelu(FFN1)
__device__ __nv_bfloat16 g_mbuf[(size_t)BROWS * CHDIM]; // FFN2∘attn output
__device__ __nv_bfloat16 g_WdT[CHDIM * CDIM];           // [n][k]
__device__ __nv_bfloat16 g_WgT[CHDIM * CDIM];
__device__ __nv_bfloat16 g_W1T[CHDIM * CHDIM];
__device__ __nv_bfloat16 g_W2T[CHDIM * CHDIM];          // (W2·Wv·Wo)^T
__device__ __nv_bfloat16 g_WuT[CDIM * CHDIM];           // (Wu + Wu·Wld·Wlu)^T
__device__ float g_P[CHDIM * CHDIM];                    // Wv@Wo
__device__ float g_T16[CHDIM * 16];                     // Wu@Wld
__device__ float g_s16[16];                             // bu@Wld
__device__ float g_b1eff[CHDIM];
__device__ float g_b2eff[CHDIM];
__device__ float g_bueff[CDIM];

// ---------------- helpers ----------------
__device__ __forceinline__ void cp8(void* s, const void* g) {
    asm volatile("cp.async.ca.shared.global [%0], [%1], 8;\n"
                 :: "r"((uint32_t)__cvta_generic_to_shared(s)), "l"(g));
}
__device__ __forceinline__ void mma_bf16(float* c, const uint32_t* a, uint32_t b0, uint32_t b1) {
    asm volatile("mma.sync.aligned.m16n8k16.row.col.f32.bf16.bf16.f32 "
                 "{%0,%1,%2,%3}, {%4,%5,%6,%7}, {%8,%9}, {%0,%1,%2,%3};\n"
                 : "+f"(c[0]), "+f"(c[1]), "+f"(c[2]), "+f"(c[3])
                 : "r"(a[0]), "r"(a[1]), "r"(a[2]), "r"(a[3]), "r"(b0), "r"(b1));
}
__device__ __forceinline__ float sigm(float x) { return 1.f / (1.f + expf(-x)); }
__device__ __forceinline__ float gelu_t(float x) {
    return 0.5f * x * (1.f + tanhf(0.7978845608028654f * (x + 0.044715f * x * x * x)));
}

// ---------------- LayerNorm: x[row,1024] -> bf16 g_t ----------------
__global__ void __launch_bounds__(256) ln_kernel(const float* __restrict__ x,
                                                 const float* __restrict__ gamma,
                                                 const float* __restrict__ beta) {
    const int row = blockIdx.x;
    const int tid = threadIdx.x;
    const float4 v = ((const float4*)(x + (size_t)row * CDIM))[tid];
    float s  = v.x + v.y + v.z + v.w;
    float s2 = v.x * v.x + v.y * v.y + v.z * v.z + v.w * v.w;
    #pragma unroll
    for (int o = 16; o > 0; o >>= 1) {
        s  += __shfl_xor_sync(0xffffffffu, s, o);
        s2 += __shfl_xor_sync(0xffffffffu, s2, o);
    }
    __shared__ float rs[8], rq[8];
    const int w = tid >> 5, lane = tid & 31;
    if (lane == 0) { rs[w] = s; rq[w] = s2; }
    __syncthreads();
    float mu = 0.f, e2 = 0.f;
    #pragma unroll
    for (int i = 0; i < 8; i++) { mu += rs[i]; e2 += rq[i]; }
    mu *= (1.f / 1024.f);
    const float var = e2 * (1.f / 1024.f) - mu * mu;
    const float rstd = rsqrtf(var + 1e-5f);
    const float4 gm = ((const float4*)gamma)[tid];
    const float4 bt = ((const float4*)beta)[tid];
    __nv_bfloat162* tp = (__nv_bfloat162*)(g_t + (size_t)row * CDIM);
    tp[tid * 2]     = __floats2bfloat162_rn((v.x - mu) * rstd * gm.x + bt.x,
                                            (v.y - mu) * rstd * gm.y + bt.y);
    tp[tid * 2 + 1] = __floats2bfloat162_rn((v.z - mu) * rstd * gm.z + bt.z,
                                            (v.w - mu) * rstd * gm.w + bt.w);
}

// ---------------- weight-composition prep kernels (tiny) ----------------
__global__ void prep_P(const float* __restrict__ Wv, const float* __restrict__ Wo) {
    __shared__ float row[256];
    const int i = blockIdx.x, j = threadIdx.x;
    row[j] = Wv[i * 256 + j];
    __syncthreads();
    float s = 0.f;
    #pragma unroll 8
    for (int k = 0; k < 256; k++) s += row[k] * Wo[k * 256 + j];
    g_P[i * 256 + j] = s;
}
__global__ void prep_W2T(const float* __restrict__ W2) {
    __shared__ float row[256];
    const int i = blockIdx.x, j = threadIdx.x;
    row[j] = W2[i * 256 + j];
    __syncthreads();
    float s = 0.f;
    #pragma unroll 8
    for (int k = 0; k < 256; k++) s += row[k] * g_P[k * 256 + j];
    g_W2T[j * 256 + i] = __float2bfloat16(s);
}
__global__ void prep_b2eff(const float* __restrict__ b2, const float* __restrict__ bv,
                           const float* __restrict__ Wo, const float* __restrict__ bo) {
    const int j = threadIdx.x;
    float s = bo[j];
    for (int k = 0; k < 256; k++) s += b2[k] * g_P[k * 256 + j] + bv[k] * Wo[k * 256 + j];
    g_b2eff[j] = s;
}
__global__ void prep_W1T(const float* __restrict__ W1, const float* __restrict__ dw_w) {
    const int i = blockIdx.x, j = threadIdx.x;
    g_W1T[j * 256 + i] = __float2bfloat16(dw_w[i] * W1[i * 256 + j]);
}
__global__ void prep_b1eff(const float* __restrict__ b1, const float* __restrict__ dw_b,
                           const float* __restrict__ W1) {
    const int j = threadIdx.x;
    float s = b1[j];
    for (int i = 0; i < 256; i++) s += dw_b[i] * W1[i * 256 + j];
    g_b1eff[j] = s;
}
__global__ void prep_T16(const float* __restrict__ Wu, const float* __restrict__ Wld) {
    const int i = blockIdx.x, tid = threadIdx.x;
    const int r = tid & 15, kc = tid >> 4;
    float s = 0.f;
    for (int k = kc * 64; k < kc * 64 + 64; k++) s += Wu[(size_t)i * 1024 + k] * Wld[k * 16 + r];
    __shared__ float buf[256];
    buf[tid] = s;
    __syncthreads();
    if (tid < 16) {
        float t = 0.f;
        #pragma unroll
        for (int c = 0; c < 16; c++) t += buf[c * 16 + tid];
        g_T16[i * 16 + tid] = t;
    }
}
__global__ void prep_s16(const float* __restrict__ bu, const float* __restrict__ Wld) {
    const int r = threadIdx.x;
    float s = 0.f;
    for (int k = 0; k < 1024; k++) s += bu[k] * Wld[k * 16 + r];
    g_s16[r] = s;
}
__global__ void prep_WuT(const float* __restrict__ Wu, const float* __restrict__ Wlu,
                         const float* __restrict__ bu) {
    const int n = blockIdx.x, i = threadIdx.x;
    __shared__ float wl[16];
    if (i < 16) wl[i] = Wlu[i * 1024 + n];
    __syncthreads();
    float s = Wu[(size_t)i * 1024 + n];
    #pragma unroll
    for (int r = 0; r < 16; r++) s += g_T16[i * 16 + r] * wl[r];
    g_WuT[n * 256 + i] = __float2bfloat16(s);
    if (i == 0) {
        float b = bu[n];
        #pragma unroll
        for (int r = 0; r < 16; r++) b += g_s16[r] * wl[r];
        g_bueff[n] = b;
    }
}
__global__ void prep_WT(const float* __restrict__ W, __nv_bfloat16* __restrict__ out) {
    const int idx = blockIdx.x * 256 + threadIdx.x;  // idx = n*1024 + k
    const int k = idx & 1023, n = idx >> 10;
    out[idx] = __float2bfloat16(W[k * 256 + n]);
}

// ---------------- tiled bf16 GEMM: C[M,N] = A[M,K] @ B^T(row n, col k) + epi ----------------
// MODE 0: GLU   h = (accA+bd)*sigmoid(accB+bg)  -> bf16   (NB=2, NCTA=64 per matrix)
// MODE 1: gelu(acc+bias)                        -> bf16
// MODE 2: acc+bias                              -> bf16
// MODE 3: 0.5*(acc+bias) + 0.5*x               -> fp32
template<int KDIM, int NCTA, int NB, int MODE>
__global__ void __launch_bounds__(256) gemm_k(
    const __nv_bfloat16* __restrict__ A,
    const __nv_bfloat16* __restrict__ BT0,
    const __nv_bfloat16* __restrict__ BT1,
    const float* __restrict__ bias0,
    const float* __restrict__ bias1,
    const float* __restrict__ xres,
    __nv_bfloat16* __restrict__ outb,
    float* __restrict__ outf) {
    constexpr int KT = 32;
    constexpr int LDS_ = KT + 8;                 // 40 elems (80B rows): conflict-free frag loads
    constexpr int NJ = (NCTA / 2) / 8;
    constexpr int NKT = KDIM / KT;
    constexpr int LDO = (MODE == 3) ? 1024 : 256;
    static_assert(NB * NCTA == 128, "flat B tile must be 128 rows");

    __shared__ __nv_bfloat16 As[2][128][LDS_];
    __shared__ __nv_bfloat16 Bs[2][128][LDS_];

    const int tid = threadIdx.x;
    const int lane = tid & 31;
    const int w = tid >> 5;
    const int wm = w >> 1, wn = w & 1;           // 4x2 warp grid
    const int g = lane >> 2, tg = lane & 3;
    const int mbase = blockIdx.y * 128;          // N-fast grid: x = n-tile, y = m-tile
    const int nbase = blockIdx.x * NCTA;

    float acc[NB][2][NJ][4];
    #pragma unroll
    for (int b = 0; b < NB; b++)
        #pragma unroll
        for (int mi = 0; mi < 2; mi++)
            #pragma unroll
            for (int nj = 0; nj < NJ; nj++)
                #pragma unroll
                for (int q = 0; q < 4; q++) acc[b][mi][nj][q] = 0.f;

    auto load_tile = [&](int s, int kt) {
        const int k0 = kt * KT;
        #pragma unroll
        for (int i = 0; i < 4; i++) {            // A: 128 rows x 8 chunks(8B)
            const int cid = tid + i * 256;
            const int r = cid >> 3, c = (cid & 7) * 4;
            cp8(&As[s][r][c], A + (size_t)(mbase + r) * KDIM + k0 + c);
        }
        #pragma unroll
        for (int i = 0; i < 4; i++) {            // B: NB*NCTA = 128 flat rows
            const int cid = tid + i * 256;
            const int fr = cid >> 3, c = (cid & 7) * 4;
            const __nv_bfloat16* bt;
            int n;
            if (NB == 2) { bt = (fr < NCTA) ? BT0 : BT1; n = fr & (NCTA - 1); }
            else         { bt = BT0; n = fr; }
            cp8(&Bs[s][fr][c], bt + (size_t)(nbase + n) * KDIM + k0 + c);
        }
        asm volatile("cp.async.commit_group;\n");
    };

    load_tile(0, 0);
    for (int kt = 0; kt < NKT; kt++) {
        const int s = kt & 1;
        if (kt + 1 < NKT) {
            load_tile(s ^ 1, kt + 1);
            asm volatile("cp.async.wait_group 1;\n");
        } else {
            asm volatile("cp.async.wait_group 0;\n");
        }
        __syncthreads();
        #pragma unroll
        for (int kk = 0; kk < KT; kk += 16) {
            uint32_t af[2][4];
            #pragma unroll
            for (int mi = 0; mi < 2; mi++) {
                const int r = wm * 32 + mi * 16 + g;
                const __nv_bfloat16* ap = &As[s][r][kk + tg * 2];
                af[mi][0] = *(const uint32_t*)ap;
                af[mi][1] = *(const uint32_t*)(ap + 8 * LDS_);
                af[mi][2] = *(const uint32_t*)(ap + 8);
                af[mi][3] = *(const uint32_t*)(ap + 8 * LDS_ + 8);
            }
            #pragma unroll
            for (int b = 0; b < NB; b++) {
                #pragma unroll
                for (int nj = 0; nj < NJ; nj++) {
                    const int n = b * NCTA + wn * (NCTA / 2) + nj * 8 + g;
                    const __nv_bfloat16* bp = &Bs[s][n][kk + tg * 2];
                    const uint32_t b0 = *(const uint32_t*)bp;
                    const uint32_t b1 = *(const uint32_t*)(bp + 8);
                    mma_bf16(acc[b][0][nj], af[0], b0, b1);
                    mma_bf16(acc[b][1][nj], af[1], b0, b1);
                }
            }
        }
        __syncthreads();
    }

    // ----- epilogue -----
    #pragma unroll
    for (int mi = 0; mi < 2; mi++) {
        #pragma unroll
        for (int nj = 0; nj < NJ; nj++) {
            const int ncol = nbase + wn * (NCTA / 2) + nj * 8 + tg * 2;
            const int r0 = mbase + wm * 32 + mi * 16 + g;
            const int r1 = r0 + 8;
            if constexpr (MODE == 0) {
                const float bda = bias0[ncol], bdb = bias0[ncol + 1];
                const float bga = bias1[ncol], bgb = bias1[ncol + 1];
                const float* aa = acc[0][mi][nj];
                const float* ab = acc[NB - 1][mi][nj];
                const float v00 = (aa[0] + bda) * sigm(ab[0] + bga);
                const float v01 = (aa[1] + bdb) * sigm(ab[1] + bgb);
                const float v10 = (aa[2] + bda) * sigm(ab[2] + bga);
                const float v11 = (aa[3] + bdb) * sigm(ab[3] + bgb);
                *(__nv_bfloat162*)&outb[(size_t)r0 * LDO + ncol] = __floats2bfloat162_rn(v00, v01);
                *(__nv_bfloat162*)&outb[(size_t)r1 * LDO + ncol] = __floats2bfloat162_rn(v10, v11);
            } else if constexpr (MODE == 1 || MODE == 2) {
                const float ba = bias0[ncol], bb = bias0[ncol + 1];
                const float* a = acc[0][mi][nj];
                float v00 = a[0] + ba, v01 = a[1] + bb, v10 = a[2] + ba, v11 = a[3] + bb;
                if constexpr (MODE == 1) {
                    v00 = gelu_t(v00); v01 = gelu_t(v01); v10 = gelu_t(v10); v11 = gelu_t(v11);
                }
                *(__nv_bfloat162*)&outb[(size_t)r0 * LDO + ncol] = __floats2bfloat162_rn(v00, v01);
                *(__nv_bfloat162*)&outb[(size_t)r1 * LDO + ncol] = __floats2bfloat162_rn(v10, v11);
            } else {
                const float ba = bias0[ncol], bb = bias0[ncol + 1];
                const float* a = acc[0][mi][nj];
                const float2 x0 = *(const float2*)&xres[(size_t)r0 * LDO + ncol];
                const float2 x1 = *(const float2*)&xres[(size_t)r1 * LDO + ncol];
                const float2 o0 = make_float2(0.5f * (a[0] + ba) + 0.5f * x0.x,
                                              0.5f * (a[1] + bb) + 0.5f * x0.y);
                const float2 o1 = make_float2(0.5f * (a[2] + ba) + 0.5f * x1.x,
                                              0.5f * (a[3] + bb) + 0.5f * x1.y);
                *(float2*)&outf[(size_t)r0 * LDO + ncol] = o0;
                *(float2*)&outf[(size_t)r1 * LDO + ncol] = o1;
            }
        }
    }
}

// ---------------- launch ----------------
extern "C" void kernel_launch(void* const* d_in, const int* in_sizes, int n_in,
                              void* d_out, int out_size) {
    (void)in_sizes; (void)n_in; (void)out_size;
    const float* x    = (const float*)d_in[0];
    const float* ln_g = (const float*)d_in[1];
    const float* ln_b = (const float*)d_in[2];
    const float* Wd   = (const float*)d_in[3];
    const float* bd   = (const float*)d_in[4];
    const float* Wg   = (const float*)d_in[5];
    const float* bg   = (const float*)d_in[6];
    const float* dww  = (const float*)d_in[7];
    const float* dwb  = (const float*)d_in[8];
    const float* W1   = (const float*)d_in[9];
    const float* b1   = (const float*)d_in[10];
    const float* W2   = (const float*)d_in[11];
    const float* b2   = (const float*)d_in[12];
    // d_in[13..16] = Wq, bq, Wk, bk : mathematically dead (softmax over 1 key == 1)
    const float* Wv   = (const float*)d_in[17];
    const float* bv   = (const float*)d_in[18];
    const float* Wo   = (const float*)d_in[19];
    const float* bo   = (const float*)d_in[20];
    const float* Wu   = (const float*)d_in[21];
    const float* bu   = (const float*)d_in[22];
    const float* Wld  = (const float*)d_in[23];
    const float* Wlu  = (const float*)d_in[24];
    float* out = (float*)d_out;

    void *p_t, *p_h, *p_g, *p_m, *p_WdT, *p_WgT, *p_W1T, *p_W2T, *p_WuT, *p_b1, *p_b2, *p_bu;
    cudaGetSymbolAddress(&p_t,   g_t);
    cudaGetSymbolAddress(&p_h,   g_hbuf);
    cudaGetSymbolAddress(&p_g,   g_gbuf);
    cudaGetSymbolAddress(&p_m,   g_mbuf);
    cudaGetSymbolAddress(&p_WdT, g_WdT);
    cudaGetSymbolAddress(&p_WgT, g_WgT);
    cudaGetSymbolAddress(&p_W1T, g_W1T);
    cudaGetSymbolAddress(&p_W2T, g_W2T);
    cudaGetSymbolAddress(&p_WuT, g_WuT);
    cudaGetSymbolAddress(&p_b1,  g_b1eff);
    cudaGetSymbolAddress(&p_b2,  g_b2eff);
    cudaGetSymbolAddress(&p_bu,  g_bueff);

    // weight composition (tiny)
    prep_P   <<<256, 256>>>(Wv, Wo);
    prep_W2T <<<256, 256>>>(W2);
    prep_b2eff<<<1, 256>>>(b2, bv, Wo, bo);
    prep_W1T <<<256, 256>>>(W1, dww);
    prep_b1eff<<<1, 256>>>(b1, dwb, W1);
    prep_T16 <<<256, 256>>>(Wu, Wld);
    prep_s16 <<<1, 16>>>(bu, Wld);
    prep_WuT <<<1024, 256>>>(Wu, Wlu, bu);
    prep_WT  <<<1024, 256>>>(Wd, (__nv_bfloat16*)p_WdT);
    prep_WT  <<<1024, 256>>>(Wg, (__nv_bfloat16*)p_WgT);

    // main chain
    ln_kernel<<<BROWS, 256>>>(x, ln_g, ln_b);
    gemm_k<1024, 64, 2, 0><<<dim3(4, 256), 256>>>(
        (const __nv_bfloat16*)p_t, (const __nv_bfloat16*)p_WdT, (const __nv_bfloat16*)p_WgT,
        bd, bg, nullptr, (__nv_bfloat16*)p_h, nullptr);
    gemm_k<256, 128, 1, 1><<<dim3(2, 256), 256>>>(
        (const __nv_bfloat16*)p_h, (const __nv_bfloat16*)p_W1T, nullptr,
        (const float*)p_b1, nullptr, nullptr, (__nv_bfloat16*)p_g, nullptr);
    gemm_k<256, 128, 1, 2><<<dim3(2, 256), 256>>>(
        (const __nv_bfloat16*)p_g, (const __nv_bfloat16*)p_W2T, nullptr,
        (const float*)p_b2, nullptr, nullptr, (__nv_bfloat16*)p_m, nullptr);
    gemm_k<256, 128, 1, 3><<<dim3(8, 256), 256>>>(
        (const __nv_bfloat16*)p_m, (const __nv_bfloat16*)p_WuT, nullptr,
        (const float*)p_bu, nullptr, x, nullptr, out);
}

// round 3
// speedup vs baseline: 1.2218x; 1.2218x over previous
#include <cuda_runtime.h>
#include <cuda_bf16.h>
#include <cstdint>

#define BROWS 32768
#define CDIM  1024
#define CHDIM 256

// ---------------- scratch (device globals; no allocations allowed) ----------------
__device__ __nv_bfloat16 g_t[(size_t)BROWS * CDIM];     // LN output, bf16
__device__ __nv_bfloat16 g_hbuf[(size_t)BROWS * CHDIM]; // GLU output
__device__ __nv_bfloat16 g_gbuf[(size_t)BROWS * CHDIM]; // gelu(FFN1)
__device__ __nv_bfloat16 g_mbuf[(size_t)BROWS * CHDIM]; // FFN2∘attn output
__device__ __nv_bfloat16 g_Wdg[512 * CDIM];             // interleaved [2j]=WdT_j,[2j+1]=WgT_j (K-major)
__device__ float         g_bdg[512];                    // interleaved bd/bg
__device__ __nv_bfloat16 g_W1T[CHDIM * CHDIM];          // [n][k]
__device__ __nv_bfloat16 g_W2T[CHDIM * CHDIM];          // (W2·Wv·Wo)^T
__device__ __nv_bfloat16 g_WuT[CDIM * CHDIM];           // (Wu + Wu·Wld·Wlu)^T
__device__ float g_P[CHDIM * CHDIM];                    // Wv@Wo
__device__ float g_T16[CHDIM * 16];                     // Wu@Wld
__device__ float g_s16[16];                             // bu@Wld
__device__ float g_b1eff[CHDIM];
__device__ float g_b2eff[CHDIM];
__device__ float g_bueff[CDIM];

// ---------------- helpers ----------------
__device__ __forceinline__ void cp16cg(uint32_t s, const void* g) {
    asm volatile("cp.async.cg.shared.global [%0], [%1], 16;\n" :: "r"(s), "l"(g));
}
__device__ __forceinline__ void cp16ca(uint32_t s, const void* g) {
    asm volatile("cp.async.ca.shared.global [%0], [%1], 16;\n" :: "r"(s), "l"(g));
}
__device__ __forceinline__ void ldsm4(uint32_t* r, uint32_t addr) {
    asm volatile("ldmatrix.sync.aligned.m8n8.x4.shared.b16 {%0,%1,%2,%3}, [%4];"
                 : "=r"(r[0]), "=r"(r[1]), "=r"(r[2]), "=r"(r[3]) : "r"(addr));
}
__device__ __forceinline__ void mma_bf16(float* c, const uint32_t* a, uint32_t b0, uint32_t b1) {
    asm volatile("mma.sync.aligned.m16n8k16.row.col.f32.bf16.bf16.f32 "
                 "{%0,%1,%2,%3}, {%4,%5,%6,%7}, {%8,%9}, {%0,%1,%2,%3};\n"
                 : "+f"(c[0]), "+f"(c[1]), "+f"(c[2]), "+f"(c[3])
                 : "r"(a[0]), "r"(a[1]), "r"(a[2]), "r"(a[3]), "r"(b0), "r"(b1));
}
__device__ __forceinline__ float sigm(float x) { return 1.f / (1.f + expf(-x)); }
__device__ __forceinline__ float gelu_t(float x) {
    return 0.5f * x * (1.f + tanhf(0.7978845608028654f * (x + 0.044715f * x * x * x)));
}

// ---------------- LayerNorm: x[row,1024] -> bf16 g_t ----------------
__global__ void __launch_bounds__(256) ln_kernel(const float* __restrict__ x,
                                                 const float* __restrict__ gamma,
                                                 const float* __restrict__ beta) {
    const int row = blockIdx.x;
    const int tid = threadIdx.x;
    const float4 v = ((const float4*)(x + (size_t)row * CDIM))[tid];
    float s  = v.x + v.y + v.z + v.w;
    float s2 = v.x * v.x + v.y * v.y + v.z * v.z + v.w * v.w;
    #pragma unroll
    for (int o = 16; o > 0; o >>= 1) {
        s  += __shfl_xor_sync(0xffffffffu, s, o);
        s2 += __shfl_xor_sync(0xffffffffu, s2, o);
    }
    __shared__ float rs[8], rq[8];
    const int w = tid >> 5, lane = tid & 31;
    if (lane == 0) { rs[w] = s; rq[w] = s2; }
    __syncthreads();
    float mu = 0.f, e2 = 0.f;
    #pragma unroll
    for (int i = 0; i < 8; i++) { mu += rs[i]; e2 += rq[i]; }
    mu *= (1.f / 1024.f);
    const float var = e2 * (1.f / 1024.f) - mu * mu;
    const float rstd = rsqrtf(var + 1e-5f);
    const float4 gm = ((const float4*)gamma)[tid];
    const float4 bt = ((const float4*)beta)[tid];
    __nv_bfloat162* tp = (__nv_bfloat162*)(g_t + (size_t)row * CDIM);
    tp[tid * 2]     = __floats2bfloat162_rn((v.x - mu) * rstd * gm.x + bt.x,
                                            (v.y - mu) * rstd * gm.y + bt.y);
    tp[tid * 2 + 1] = __floats2bfloat162_rn((v.z - mu) * rstd * gm.z + bt.z,
                                            (v.w - mu) * rstd * gm.w + bt.w);
}

// ---------------- weight-composition prep kernels (tiny) ----------------
__global__ void prep_P(const float* __restrict__ Wv, const float* __restrict__ Wo) {
    __shared__ float row[256];
    const int i = blockIdx.x, j = threadIdx.x;
    row[j] = Wv[i * 256 + j];
    __syncthreads();
    float s = 0.f;
    #pragma unroll 8
    for (int k = 0; k < 256; k++) s += row[k] * Wo[k * 256 + j];
    g_P[i * 256 + j] = s;
}
__global__ void prep_W2T(const float* __restrict__ W2) {
    __shared__ float row[256];
    const int i = blockIdx.x, j = threadIdx.x;
    row[j] = W2[i * 256 + j];
    __syncthreads();
    float s = 0.f;
    #pragma unroll 8
    for (int k = 0; k < 256; k++) s += row[k] * g_P[k * 256 + j];
    g_W2T[j * 256 + i] = __float2bfloat16(s);
}
__global__ void prep_b2eff(const float* __restrict__ b2, const float* __restrict__ bv,
                           const float* __restrict__ Wo, const float* __restrict__ bo) {
    const int j = threadIdx.x;
    float s = bo[j];
    for (int k = 0; k < 256; k++) s += b2[k] * g_P[k * 256 + j] + bv[k] * Wo[k * 256 + j];
    g_b2eff[j] = s;
}
__global__ void prep_W1T(const float* __restrict__ W1, const float* __restrict__ dw_w) {
    const int i = blockIdx.x, j = threadIdx.x;
    g_W1T[j * 256 + i] = __float2bfloat16(dw_w[i] * W1[i * 256 + j]);
}
__global__ void prep_b1eff(const float* __restrict__ b1, const float* __restrict__ dw_b,
                           const float* __restrict__ W1) {
    const int j = threadIdx.x;
    float s = b1[j];
    for (int i = 0; i < 256; i++) s += dw_b[i] * W1[i * 256 + j];
    g_b1eff[j] = s;
}
__global__ void prep_T16(const float* __restrict__ Wu, const float* __restrict__ Wld) {
    const int i = blockIdx.x, tid = threadIdx.x;
    const int r = tid & 15, kc = tid >> 4;
    float s = 0.f;
    for (int k = kc * 64; k < kc * 64 + 64; k++) s += Wu[(size_t)i * 1024 + k] * Wld[k * 16 + r];
    __shared__ float buf[256];
    buf[tid] = s;
    __syncthreads();
    if (tid < 16) {
        float t = 0.f;
        #pragma unroll
        for (int c = 0; c < 16; c++) t += buf[c * 16 + tid];
        g_T16[i * 16 + tid] = t;
    }
}
__global__ void prep_s16(const float* __restrict__ bu, const float* __restrict__ Wld) {
    const int r = threadIdx.x;
    float s = 0.f;
    for (int k = 0; k < 1024; k++) s += bu[k] * Wld[k * 16 + r];
    g_s16[r] = s;
}
__global__ void prep_WuT(const float* __restrict__ Wu, const float* __restrict__ Wlu,
                         const float* __restrict__ bu) {
    const int n = blockIdx.x, i = threadIdx.x;
    __shared__ float wl[16];
    if (i < 16) wl[i] = Wlu[i * 1024 + n];
    __syncthreads();
    float s = Wu[(size_t)i * 1024 + n];
    #pragma unroll
    for (int r = 0; r < 16; r++) s += g_T16[i * 16 + r] * wl[r];
    g_WuT[n * 256 + i] = __float2bfloat16(s);
    if (i == 0) {
        float b = bu[n];
        #pragma unroll
        for (int r = 0; r < 16; r++) b += g_s16[r] * wl[r];
        g_bueff[n] = b;
    }
}
__global__ void prep_Wdg(const float* __restrict__ Wd, const float* __restrict__ Wg) {
    const int idx = blockIdx.x * 256 + threadIdx.x;  // 512*1024 elems
    const int f = idx >> 10, k = idx & 1023;
    const int j = f >> 1;
    const float* W = (f & 1) ? Wg : Wd;
    g_Wdg[idx] = __float2bfloat16(W[k * 256 + j]);
}
__global__ void prep_bdg(const float* __restrict__ bd, const float* __restrict__ bg) {
    const int t = threadIdx.x;
    g_bdg[t] = (t & 1) ? bg[t >> 1] : bd[t >> 1];
}

// ---------------- HMMA GEMM: 128x128 CTA tile, KT=64, 3-stage cp.async, ldmatrix ----------------
// smem layout per stage: rows of 64 bf16 (128B), SW128 swizzle (off ^= (off>>3)&0x70).
// warp grid 2(m) x 4(n): warp tile 64x32 -> mi=4, nj=4, 16 MMA per k16 step.
// MODE 0: GLU over interleaved (d,g) adjacent columns -> bf16 [.,256]
// MODE 1: gelu(acc+bias) -> bf16   MODE 2: acc+bias -> bf16
// MODE 3: 0.5*(acc+bias) + 0.5*x -> fp32 [.,1024]
template<int KDIM, int MODE>
__global__ void __launch_bounds__(256, 2) gemm_hmma(
    const __nv_bfloat16* __restrict__ A,
    const __nv_bfloat16* __restrict__ BT,
    const float* __restrict__ bias,
    const float* __restrict__ xres,
    __nv_bfloat16* __restrict__ outb,
    float* __restrict__ outf) {
    constexpr int NKT = KDIM / 64;
    extern __shared__ __align__(1024) char dsm[];
    const uint32_t Ab = (uint32_t)__cvta_generic_to_shared(dsm);       // [3][128][64]
    const uint32_t Bb = Ab + 49152;                                    // [3][128][64]
    const int tid = threadIdx.x, lane = tid & 31, w = tid >> 5;
    const int wm = w >> 2, wn = w & 3;
    const int mbase = blockIdx.y * 128, nbase = blockIdx.x * 128;

    float acc[4][4][4];
    #pragma unroll
    for (int mi = 0; mi < 4; mi++)
        #pragma unroll
        for (int nj = 0; nj < 4; nj++)
            #pragma unroll
            for (int q = 0; q < 4; q++) acc[mi][nj][q] = 0.f;

    auto fill = [&](int s, int c) {
        const int k0 = c * 64;
        #pragma unroll
        for (int i = 0; i < 4; i++) {
            const int cid = tid + i * 256;
            const int rr = cid >> 3, cc = cid & 7;
            uint32_t off = (uint32_t)(rr * 128 + cc * 16);
            off ^= (off >> 3) & 0x70;
            cp16cg(Ab + s * 16384 + off, A + (size_t)(mbase + rr) * KDIM + k0 + cc * 8);
        }
        #pragma unroll
        for (int i = 0; i < 4; i++) {
            const int cid = tid + i * 256;
            const int rr = cid >> 3, cc = cid & 7;
            uint32_t off = (uint32_t)(rr * 128 + cc * 16);
            off ^= (off >> 3) & 0x70;
            cp16ca(Bb + s * 16384 + off, BT + (size_t)(nbase + rr) * KDIM + k0 + cc * 8);
        }
        asm volatile("cp.async.commit_group;\n" ::: "memory");
    };

    // per-thread ldmatrix address components
    const int a_r  = wm * 64 + ((lane >> 3) & 1) * 8 + (lane & 7);   // + mi*16
    const int a_cb = ((lane >> 4) & 1) * 16;                         // + kk*32 bytes
    const int b_r  = wn * 32 + ((lane >> 4) & 1) * 8 + (lane & 7);   // + njp*16
    const int b_cb = ((lane >> 3) & 1) * 16;

    fill(0, 0);
    fill(1, 1);
    int fi = 2;
    for (int i = 0; i < NKT; i++) {
        const int s = i % 3;
        if (i < NKT - 1) asm volatile("cp.async.wait_group 1;\n" ::: "memory");
        else             asm volatile("cp.async.wait_group 0;\n" ::: "memory");
        __syncthreads();
        if (fi < NKT) { fill(fi % 3, fi); fi++; }
        const uint32_t As = Ab + s * 16384, Bs = Bb + s * 16384;
        #pragma unroll
        for (int kk = 0; kk < 4; kk++) {
            uint32_t a[4][4], b[2][4];
            #pragma unroll
            for (int mi = 0; mi < 4; mi++) {
                uint32_t off = (uint32_t)((a_r + mi * 16) * 128 + a_cb + kk * 32);
                off ^= (off >> 3) & 0x70;
                ldsm4(a[mi], As + off);
            }
            #pragma unroll
            for (int njp = 0; njp < 2; njp++) {
                uint32_t off = (uint32_t)((b_r + njp * 16) * 128 + b_cb + kk * 32);
                off ^= (off >> 3) & 0x70;
                ldsm4(b[njp], Bs + off);
            }
            #pragma unroll
            for (int mi = 0; mi < 4; mi++)
                #pragma unroll
                for (int nj = 0; nj < 4; nj++)
                    mma_bf16(acc[mi][nj], a[mi], b[nj >> 1][(nj & 1) * 2],
                             b[nj >> 1][(nj & 1) * 2 + 1]);
        }
    }

    // ----- epilogue (register -> gmem) -----
    #pragma unroll
    for (int mi = 0; mi < 4; mi++) {
        const int r0 = mbase + wm * 64 + mi * 16 + (lane >> 2);
        const int r1 = r0 + 8;
        #pragma unroll
        for (int nj = 0; nj < 4; nj++) {
            const int col = nbase + wn * 32 + nj * 8 + (lane & 3) * 2;
            const float* c = acc[mi][nj];
            if constexpr (MODE == 0) {
                const float b0 = bias[col], b1 = bias[col + 1];
                const int j = col >> 1;
                outb[(size_t)r0 * 256 + j] = __float2bfloat16((c[0] + b0) * sigm(c[1] + b1));
                outb[(size_t)r1 * 256 + j] = __float2bfloat16((c[2] + b0) * sigm(c[3] + b1));
            } else if constexpr (MODE == 1 || MODE == 2) {
                const float b0 = bias[col], b1 = bias[col + 1];
                float v00 = c[0] + b0, v01 = c[1] + b1, v10 = c[2] + b0, v11 = c[3] + b1;
                if constexpr (MODE == 1) {
                    v00 = gelu_t(v00); v01 = gelu_t(v01); v10 = gelu_t(v10); v11 = gelu_t(v11);
                }
                *(__nv_bfloat162*)&outb[(size_t)r0 * 256 + col] = __floats2bfloat162_rn(v00, v01);
                *(__nv_bfloat162*)&outb[(size_t)r1 * 256 + col] = __floats2bfloat162_rn(v10, v11);
            } else {
                const float b0 = bias[col], b1 = bias[col + 1];
                const float2 x0 = *(const float2*)&xres[(size_t)r0 * 1024 + col];
                const float2 x1 = *(const float2*)&xres[(size_t)r1 * 1024 + col];
                float2 o0 = make_float2(0.5f * (c[0] + b0) + 0.5f * x0.x,
                                        0.5f * (c[1] + b1) + 0.5f * x0.y);
                float2 o1 = make_float2(0.5f * (c[2] + b0) + 0.5f * x1.x,
                                        0.5f * (c[3] + b1) + 0.5f * x1.y);
                *(float2*)&outf[(size_t)r0 * 1024 + col] = o0;
                *(float2*)&outf[(size_t)r1 * 1024 + col] = o1;
            }
        }
    }
}

// ---------------- launch ----------------
extern "C" void kernel_launch(void* const* d_in, const int* in_sizes, int n_in,
                              void* d_out, int out_size) {
    (void)in_sizes; (void)n_in; (void)out_size;
    const float* x    = (const float*)d_in[0];
    const float* ln_g = (const float*)d_in[1];
    const float* ln_b = (const float*)d_in[2];
    const float* Wd   = (const float*)d_in[3];
    const float* bd   = (const float*)d_in[4];
    const float* Wg   = (const float*)d_in[5];
    const float* bg   = (const float*)d_in[6];
    const float* dww  = (const float*)d_in[7];
    const float* dwb  = (const float*)d_in[8];
    const float* W1   = (const float*)d_in[9];
    const float* b1   = (const float*)d_in[10];
    const float* W2   = (const float*)d_in[11];
    const float* b2   = (const float*)d_in[12];
    // d_in[13..16] = Wq, bq, Wk, bk : dead (softmax over a single key == 1)
    const float* Wv   = (const float*)d_in[17];
    const float* bv   = (const float*)d_in[18];
    const float* Wo   = (const float*)d_in[19];
    const float* bo   = (const float*)d_in[20];
    const float* Wu   = (const float*)d_in[21];
    const float* bu   = (const float*)d_in[22];
    const float* Wld  = (const float*)d_in[23];
    const float* Wlu  = (const float*)d_in[24];
    float* out = (float*)d_out;

    void *p_t, *p_h, *p_g, *p_m, *p_Wdg, *p_bdg, *p_W1T, *p_W2T, *p_WuT, *p_b1, *p_b2, *p_bu;
    cudaGetSymbolAddress(&p_t,   g_t);
    cudaGetSymbolAddress(&p_h,   g_hbuf);
    cudaGetSymbolAddress(&p_g,   g_gbuf);
    cudaGetSymbolAddress(&p_m,   g_mbuf);
    cudaGetSymbolAddress(&p_Wdg, g_Wdg);
    cudaGetSymbolAddress(&p_bdg, g_bdg);
    cudaGetSymbolAddress(&p_W1T, g_W1T);
    cudaGetSymbolAddress(&p_W2T, g_W2T);
    cudaGetSymbolAddress(&p_WuT, g_WuT);
    cudaGetSymbolAddress(&p_b1,  g_b1eff);
    cudaGetSymbolAddress(&p_b2,  g_b2eff);
    cudaGetSymbolAddress(&p_bu,  g_bueff);

    constexpr int DSM = 98304;  // 3 stages x (16KB A + 16KB B)
    static bool attr_done = false;
    if (!attr_done) {
        cudaFuncSetAttribute(gemm_hmma<1024, 0>, cudaFuncAttributeMaxDynamicSharedMemorySize, DSM);
        cudaFuncSetAttribute(gemm_hmma<256, 1>,  cudaFuncAttributeMaxDynamicSharedMemorySize, DSM);
        cudaFuncSetAttribute(gemm_hmma<256, 2>,  cudaFuncAttributeMaxDynamicSharedMemorySize, DSM);
        cudaFuncSetAttribute(gemm_hmma<256, 3>,  cudaFuncAttributeMaxDynamicSharedMemorySize, DSM);
        attr_done = true;
    }

    // weight composition (tiny)
    prep_P    <<<256, 256>>>(Wv, Wo);
    prep_W2T  <<<256, 256>>>(W2);
    prep_b2eff<<<1, 256>>>(b2, bv, Wo, bo);
    prep_W1T  <<<256, 256>>>(W1, dww);
    prep_b1eff<<<1, 256>>>(b1, dwb, W1);
    prep_T16  <<<256, 256>>>(Wu, Wld);
    prep_s16  <<<1, 16>>>(bu, Wld);
    prep_WuT  <<<1024, 256>>>(Wu, Wlu, bu);
    prep_Wdg  <<<2048, 256>>>(Wd, Wg);
    prep_bdg  <<<1, 512>>>(bd, bg);

    // main chain (grid.x = n-tile fast so co-resident CTAs share the A tile via L2)
    ln_kernel<<<BROWS, 256>>>(x, ln_g, ln_b);
    gemm_hmma<1024, 0><<<dim3(4, 256), 256, DSM>>>(
        (const __nv_bfloat16*)p_t, (const __nv_bfloat16*)p_Wdg,
        (const float*)p_bdg, nullptr, (__nv_bfloat16*)p_h, nullptr);
    gemm_hmma<256, 1><<<dim3(2, 256), 256, DSM>>>(
        (const __nv_bfloat16*)p_h, (const __nv_bfloat16*)p_W1T,
        (const float*)p_b1, nullptr, (__nv_bfloat16*)p_g, nullptr);
    gemm_hmma<256, 2><<<dim3(2, 256), 256, DSM>>>(
        (const __nv_bfloat16*)p_g, (const __nv_bfloat16*)p_W2T,
        (const float*)p_b2, nullptr, (__nv_bfloat16*)p_m, nullptr);
    gemm_hmma<256, 3><<<dim3(8, 256), 256, DSM>>>(
        (const __nv_bfloat16*)p_m, (const __nv_bfloat16*)p_WuT,
        (const float*)p_bu, x, nullptr, out);
}

// round 4
// speedup vs baseline: 1.3337x; 1.0916x over previous
#include <cuda_runtime.h>
#include <cuda_bf16.h>
#include <cstdint>

#define BROWS 32768
#define CDIM  1024
#define CHDIM 256

// ---------------- scratch (device globals; no allocations allowed) ----------------
__device__ uint8_t g_t8[(size_t)BROWS * CDIM];    // LN output, fp8 e4m3
__device__ uint8_t g_h8[(size_t)BROWS * CHDIM];   // GLU output, fp8
__device__ uint8_t g_g8[(size_t)BROWS * CHDIM];   // gelu(FFN1), fp8
__device__ uint8_t g_m8[(size_t)BROWS * CHDIM];   // FFN2∘attn output, fp8
__device__ uint8_t g_Wdg8[512 * CDIM];            // interleaved [2j]=WdT_j,[2j+1]=WgT_j (K-major fp8)
__device__ float   g_bdg[512];                    // interleaved bd/bg
__device__ uint8_t g_W1T8[CHDIM * CHDIM];         // [n][k] fp8 (dw folded)
__device__ uint8_t g_W2T8[CHDIM * CHDIM];         // (W2·Wv·Wo)^T fp8
__device__ uint8_t g_WuT8[CDIM * CHDIM];          // (Wu + Wu·Wld·Wlu)^T fp8
__device__ float g_P[CHDIM * CHDIM];              // Wv@Wo
__device__ float g_T16[CHDIM * 16];               // Wu@Wld
__device__ float g_s16[16];                       // bu@Wld
__device__ float g_b1eff[CHDIM];
__device__ float g_b2eff[CHDIM];
__device__ float g_bueff[CDIM];

// ---------------- helpers ----------------
__device__ __forceinline__ void cp16cg(uint32_t s, const void* g) {
    asm volatile("cp.async.cg.shared.global [%0], [%1], 16;\n" :: "r"(s), "l"(g));
}
__device__ __forceinline__ void ldsm4(uint32_t* r, uint32_t addr) {
    asm volatile("ldmatrix.sync.aligned.m8n8.x4.shared.b16 {%0,%1,%2,%3}, [%4];"
                 : "=r"(r[0]), "=r"(r[1]), "=r"(r[2]), "=r"(r[3]) : "r"(addr));
}
__device__ __forceinline__ void mma_fp8(float* c, const uint32_t* a, uint32_t b0, uint32_t b1) {
    asm volatile("mma.sync.aligned.m16n8k32.row.col.f32.e4m3.e4m3.f32 "
                 "{%0,%1,%2,%3}, {%4,%5,%6,%7}, {%8,%9}, {%0,%1,%2,%3};\n"
                 : "+f"(c[0]), "+f"(c[1]), "+f"(c[2]), "+f"(c[3])
                 : "r"(a[0]), "r"(a[1]), "r"(a[2]), "r"(a[3]), "r"(b0), "r"(b1));
}
__device__ __forceinline__ uint16_t pk_e4m3_2(float lo, float hi) {
    uint16_t r;
    asm("cvt.rn.satfinite.e4m3x2.f32 %0, %1, %2;" : "=h"(r) : "f"(hi), "f"(lo));
    return r;
}
__device__ __forceinline__ uint32_t pk_e4m3_4(float a, float b, float c, float d) {
    return (uint32_t)pk_e4m3_2(a, b) | ((uint32_t)pk_e4m3_2(c, d) << 16);
}
__device__ __forceinline__ uint8_t pk_e4m3_1(float v) {
    return (uint8_t)pk_e4m3_2(v, 0.f);
}
__device__ __forceinline__ float sigm(float x) { return 1.f / (1.f + expf(-x)); }
__device__ __forceinline__ float gelu_t(float x) {
    return 0.5f * x * (1.f + tanhf(0.7978845608028654f * (x + 0.044715f * x * x * x)));
}

// ---------------- merged prep kernels (launch indices 0-3) ----------------
// prepA1: blocks [0,256) P=Wv@Wo ; [256,512) W1T8 (dw folded) ; 512 b1eff
__global__ void __launch_bounds__(256) prepA1(
    const float* __restrict__ Wv, const float* __restrict__ Wo,
    const float* __restrict__ W1, const float* __restrict__ dww,
    const float* __restrict__ b1, const float* __restrict__ dwb) {
    __shared__ float rowbuf[256];
    const int b = blockIdx.x, j = threadIdx.x;
    if (b < 256) {
        rowbuf[j] = Wv[b * 256 + j];
        __syncthreads();
        float s = 0.f;
        #pragma unroll 8
        for (int k = 0; k < 256; k++) s += rowbuf[k] * Wo[k * 256 + j];
        g_P[b * 256 + j] = s;
    } else if (b < 512) {
        const int i = b - 256;
        g_W1T8[j * 256 + i] = pk_e4m3_1(dww[i] * W1[i * 256 + j]);
    } else {
        float s = b1[j];
        for (int i = 0; i < 256; i++) s += dwb[i] * W1[i * 256 + j];
        g_b1eff[j] = s;
    }
}
// prepA2: blocks [0,512) Wdg8 ; 512 bdg ; [513,769) T16 ; 769 s16
__global__ void __launch_bounds__(256) prepA2(
    const float* __restrict__ Wd, const float* __restrict__ Wg,
    const float* __restrict__ bd, const float* __restrict__ bg,
    const float* __restrict__ Wu, const float* __restrict__ Wld,
    const float* __restrict__ bu) {
    __shared__ float buf[256];
    const int b = blockIdx.x, t = threadIdx.x;
    if (b < 512) {
        const int j = b >> 1;
        const float* W = (b & 1) ? Wg : Wd;
        const int k0 = t * 4;
        ((uint32_t*)g_Wdg8)[b * 256 + t] = pk_e4m3_4(
            W[(k0 + 0) * 256 + j], W[(k0 + 1) * 256 + j],
            W[(k0 + 2) * 256 + j], W[(k0 + 3) * 256 + j]);
    } else if (b == 512) {
        for (int idx = t; idx < 512; idx += 256)
            g_bdg[idx] = (idx & 1) ? bg[idx >> 1] : bd[idx >> 1];
    } else if (b < 769) {
        const int i = b - 513;
        const int r = t & 15, kc = t >> 4;
        float s = 0.f;
        for (int k = kc * 64; k < kc * 64 + 64; k++)
            s += Wu[(size_t)i * 1024 + k] * Wld[k * 16 + r];
        buf[t] = s;
        __syncthreads();
        if (t < 16) {
            float acc = 0.f;
            #pragma unroll
            for (int c = 0; c < 16; c++) acc += buf[c * 16 + t];
            g_T16[i * 16 + t] = acc;
        }
    } else {
        if (t < 16) {
            float s = 0.f;
            for (int k = 0; k < 1024; k++) s += bu[k] * Wld[k * 16 + t];
            g_s16[t] = s;
        }
    }
}
// prepB1: blocks [0,256) W2T8 = (W2@P)^T fp8 ; 256 b2eff
__global__ void __launch_bounds__(256) prepB1(
    const float* __restrict__ W2, const float* __restrict__ b2,
    const float* __restrict__ bv, const float* __restrict__ Wo,
    const float* __restrict__ bo) {
    __shared__ float rowbuf[256];
    const int b = blockIdx.x, j = threadIdx.x;
    if (b < 256) {
        rowbuf[j] = W2[b * 256 + j];
        __syncthreads();
        float s = 0.f;
        #pragma unroll 8
        for (int k = 0; k < 256; k++) s += rowbuf[k] * g_P[k * 256 + j];
        g_W2T8[j * 256 + b] = pk_e4m3_1(s);
    } else {
        float s = bo[j];
        for (int k = 0; k < 256; k++) s += b2[k] * g_P[k * 256 + j] + bv[k] * Wo[k * 256 + j];
        g_b2eff[j] = s;
    }
}
// prepB2: blocks [0,1024) WuT8 rows + bueff
__global__ void __launch_bounds__(256) prepB2(
    const float* __restrict__ Wu, const float* __restrict__ Wlu,
    const float* __restrict__ bu) {
    const int n = blockIdx.x, i = threadIdx.x;
    __shared__ float wl[16];
    __shared__ float sb[256];
    if (i < 16) wl[i] = Wlu[i * 1024 + n];
    __syncthreads();
    float s = Wu[(size_t)i * 1024 + n];
    #pragma unroll
    for (int r = 0; r < 16; r++) s += g_T16[i * 16 + r] * wl[r];
    sb[i] = s;
    if (i == 0) {
        float bb = bu[n];
        #pragma unroll
        for (int r = 0; r < 16; r++) bb += g_s16[r] * wl[r];
        g_bueff[n] = bb;
    }
    __syncthreads();
    if (i < 64)
        ((uint32_t*)g_WuT8)[n * 64 + i] =
            pk_e4m3_4(sb[4 * i], sb[4 * i + 1], sb[4 * i + 2], sb[4 * i + 3]);
}

// ---------------- LayerNorm: x[row,1024] -> fp8 g_t8 (launch index 4) ----------------
__global__ void __launch_bounds__(256) ln_kernel(const float* __restrict__ x,
                                                 const float* __restrict__ gamma,
                                                 const float* __restrict__ beta) {
    const int row = blockIdx.x;
    const int tid = threadIdx.x;
    const float4 v = ((const float4*)(x + (size_t)row * CDIM))[tid];
    float s  = v.x + v.y + v.z + v.w;
    float s2 = v.x * v.x + v.y * v.y + v.z * v.z + v.w * v.w;
    #pragma unroll
    for (int o = 16; o > 0; o >>= 1) {
        s  += __shfl_xor_sync(0xffffffffu, s, o);
        s2 += __shfl_xor_sync(0xffffffffu, s2, o);
    }
    __shared__ float rs[8], rq[8];
    const int w = tid >> 5, lane = tid & 31;
    if (lane == 0) { rs[w] = s; rq[w] = s2; }
    __syncthreads();
    float mu = 0.f, e2 = 0.f;
    #pragma unroll
    for (int i = 0; i < 8; i++) { mu += rs[i]; e2 += rq[i]; }
    mu *= (1.f / 1024.f);
    const float var = e2 * (1.f / 1024.f) - mu * mu;
    const float rstd = rsqrtf(var + 1e-5f);
    const float4 gm = ((const float4*)gamma)[tid];
    const float4 bt = ((const float4*)beta)[tid];
    ((uint32_t*)(g_t8 + (size_t)row * CDIM))[tid] = pk_e4m3_4(
        (v.x - mu) * rstd * gm.x + bt.x, (v.y - mu) * rstd * gm.y + bt.y,
        (v.z - mu) * rstd * gm.z + bt.z, (v.w - mu) * rstd * gm.w + bt.w);
}

// ---------------- FP8 QMMA GEMM: 128x128 CTA tile, KT=128B, 3-stage cp.async, ldmatrix ----
// smem stage: 128 rows x 128 fp8 (128B rows, SW128 swizzle). warp grid 2(m)x4(n),
// warp tile 64x32. 4 k32-steps per stage, 16 MMA each.
// MODE 0: GLU over interleaved (d,g) adjacent cols -> fp8 [.,256]
// MODE 1: gelu(acc+bias) -> fp8   MODE 2: acc+bias -> fp8
// MODE 3: 0.5*(acc+bias) + 0.5*x -> fp32 [.,1024]
template<int KDIM, int MODE>
__global__ void __launch_bounds__(256, 2) gemm_fp8(
    const uint8_t* __restrict__ A,
    const uint8_t* __restrict__ BT,
    const float* __restrict__ bias,
    const float* __restrict__ xres,
    uint8_t* __restrict__ out8,
    float* __restrict__ outf) {
    constexpr int NKT = KDIM / 128;
    extern __shared__ __align__(1024) char dsm[];
    const uint32_t Ab = (uint32_t)__cvta_generic_to_shared(dsm);  // [3][128][128B]
    const uint32_t Bb = Ab + 49152;                               // [3][128][128B]
    const int tid = threadIdx.x, lane = tid & 31, w = tid >> 5;
    const int wm = w >> 2, wn = w & 3;
    const int mbase = blockIdx.y * 128, nbase = blockIdx.x * 128;

    float acc[4][4][4];
    #pragma unroll
    for (int mi = 0; mi < 4; mi++)
        #pragma unroll
        for (int nj = 0; nj < 4; nj++)
            #pragma unroll
            for (int q = 0; q < 4; q++) acc[mi][nj][q] = 0.f;

    auto fill = [&](int s, int c) {
        const int k0 = c * 128;
        #pragma unroll
        for (int i = 0; i < 4; i++) {
            const int cid = tid + i * 256;
            const int rr = cid >> 3, cc = cid & 7;
            uint32_t off = (uint32_t)(rr * 128 + cc * 16);
            off ^= (off >> 3) & 0x70;
            cp16cg(Ab + s * 16384 + off, A + (size_t)(mbase + rr) * KDIM + k0 + cc * 16);
        }
        #pragma unroll
        for (int i = 0; i < 4; i++) {
            const int cid = tid + i * 256;
            const int rr = cid >> 3, cc = cid & 7;
            uint32_t off = (uint32_t)(rr * 128 + cc * 16);
            off ^= (off >> 3) & 0x70;
            cp16cg(Bb + s * 16384 + off, BT + (size_t)(nbase + rr) * KDIM + k0 + cc * 16);
        }
        asm volatile("cp.async.commit_group;\n" ::: "memory");
    };

    // ldmatrix address components (b16-element view of fp8 rows)
    const int a_r  = wm * 64 + ((lane >> 3) & 1) * 8 + (lane & 7);   // + mi*16
    const int a_cb = ((lane >> 4) & 1) * 16;                         // + kk*32 bytes
    const int b_r  = wn * 32 + ((lane >> 4) & 1) * 8 + (lane & 7);   // + (njp)*16
    const int b_cb = ((lane >> 3) & 1) * 16;

    fill(0, 0);
    if (NKT > 1) fill(1, 1);
    int fi = 2;
    for (int i = 0; i < NKT; i++) {
        const int s = i % 3;
        if (i < NKT - 1) asm volatile("cp.async.wait_group 1;\n" ::: "memory");
        else             asm volatile("cp.async.wait_group 0;\n" ::: "memory");
        __syncthreads();
        if (fi < NKT) { fill(fi % 3, fi); fi++; }
        const uint32_t As = Ab + s * 16384, Bs = Bb + s * 16384;
        #pragma unroll
        for (int kk = 0; kk < 4; kk++) {             // k32 steps
            uint32_t a[4][4], b[2][4];
            #pragma unroll
            for (int mi = 0; mi < 4; mi++) {
                uint32_t off = (uint32_t)((a_r + mi * 16) * 128 + a_cb + kk * 32);
                off ^= (off >> 3) & 0x70;
                ldsm4(a[mi], As + off);
            }
            #pragma unroll
            for (int njp = 0; njp < 2; njp++) {
                uint32_t off = (uint32_t)((b_r + njp * 16) * 128 + b_cb + kk * 32);
                off ^= (off >> 3) & 0x70;
                ldsm4(b[njp], Bs + off);
            }
            #pragma unroll
            for (int mi = 0; mi < 4; mi++)
                #pragma unroll
                for (int nj = 0; nj < 4; nj++)
                    mma_fp8(acc[mi][nj], a[mi], b[nj >> 1][(nj & 1) * 2],
                            b[nj >> 1][(nj & 1) * 2 + 1]);
        }
    }

    // ----- epilogue -----
    #pragma unroll
    for (int mi = 0; mi < 4; mi++) {
        const int r0 = mbase + wm * 64 + mi * 16 + (lane >> 2);
        const int r1 = r0 + 8;
        #pragma unroll
        for (int nj = 0; nj < 4; nj++) {
            const int col = nbase + wn * 32 + nj * 8 + (lane & 3) * 2;
            const float* c = acc[mi][nj];
            if constexpr (MODE == 0) {
                const float b0 = bias[col], b1 = bias[col + 1];
                const int j = col >> 1;
                out8[(size_t)r0 * 256 + j] = pk_e4m3_1((c[0] + b0) * sigm(c[1] + b1));
                out8[(size_t)r1 * 256 + j] = pk_e4m3_1((c[2] + b0) * sigm(c[3] + b1));
            } else if constexpr (MODE == 1 || MODE == 2) {
                const float b0 = bias[col], b1 = bias[col + 1];
                float v00 = c[0] + b0, v01 = c[1] + b1, v10 = c[2] + b0, v11 = c[3] + b1;
                if constexpr (MODE == 1) {
                    v00 = gelu_t(v00); v01 = gelu_t(v01); v10 = gelu_t(v10); v11 = gelu_t(v11);
                }
                *(uint16_t*)&out8[(size_t)r0 * 256 + col] = pk_e4m3_2(v00, v01);
                *(uint16_t*)&out8[(size_t)r1 * 256 + col] = pk_e4m3_2(v10, v11);
            } else {
                const float b0 = bias[col], b1 = bias[col + 1];
                const float2 x0 = *(const float2*)&xres[(size_t)r0 * 1024 + col];
                const float2 x1 = *(const float2*)&xres[(size_t)r1 * 1024 + col];
                float2 o0 = make_float2(0.5f * (c[0] + b0) + 0.5f * x0.x,
                                        0.5f * (c[1] + b1) + 0.5f * x0.y);
                float2 o1 = make_float2(0.5f * (c[2] + b0) + 0.5f * x1.x,
                                        0.5f * (c[3] + b1) + 0.5f * x1.y);
                *(float2*)&outf[(size_t)r0 * 1024 + col] = o0;
                *(float2*)&outf[(size_t)r1 * 1024 + col] = o1;
            }
        }
    }
}

// ---------------- launch ----------------
extern "C" void kernel_launch(void* const* d_in, const int* in_sizes, int n_in,
                              void* d_out, int out_size) {
    (void)in_sizes; (void)n_in; (void)out_size;
    const float* x    = (const float*)d_in[0];
    const float* ln_g = (const float*)d_in[1];
    const float* ln_b = (const float*)d_in[2];
    const float* Wd   = (const float*)d_in[3];
    const float* bd   = (const float*)d_in[4];
    const float* Wg   = (const float*)d_in[5];
    const float* bg   = (const float*)d_in[6];
    const float* dww  = (const float*)d_in[7];
    const float* dwb  = (const float*)d_in[8];
    const float* W1   = (const float*)d_in[9];
    const float* b1   = (const float*)d_in[10];
    const float* W2   = (const float*)d_in[11];
    const float* b2   = (const float*)d_in[12];
    // d_in[13..16] = Wq, bq, Wk, bk : dead (softmax over a single key == 1)
    const float* Wv   = (const float*)d_in[17];
    const float* bv   = (const float*)d_in[18];
    const float* Wo   = (const float*)d_in[19];
    const float* bo   = (const float*)d_in[20];
    const float* Wu   = (const float*)d_in[21];
    const float* bu   = (const float*)d_in[22];
    const float* Wld  = (const float*)d_in[23];
    const float* Wlu  = (const float*)d_in[24];
    float* out = (float*)d_out;

    void *p_t, *p_h, *p_g, *p_m, *p_Wdg, *p_bdg, *p_W1, *p_W2, *p_Wu, *p_b1, *p_b2, *p_bu;
    cudaGetSymbolAddress(&p_t,   g_t8);
    cudaGetSymbolAddress(&p_h,   g_h8);
    cudaGetSymbolAddress(&p_g,   g_g8);
    cudaGetSymbolAddress(&p_m,   g_m8);
    cudaGetSymbolAddress(&p_Wdg, g_Wdg8);
    cudaGetSymbolAddress(&p_bdg, g_bdg);
    cudaGetSymbolAddress(&p_W1,  g_W1T8);
    cudaGetSymbolAddress(&p_W2,  g_W2T8);
    cudaGetSymbolAddress(&p_Wu,  g_WuT8);
    cudaGetSymbolAddress(&p_b1,  g_b1eff);
    cudaGetSymbolAddress(&p_b2,  g_b2eff);
    cudaGetSymbolAddress(&p_bu,  g_bueff);

    constexpr int DSM = 98304;  // 3 stages x (16KB A + 16KB B)
    static bool attr_done = false;
    if (!attr_done) {
        cudaFuncSetAttribute(gemm_fp8<1024, 0>, cudaFuncAttributeMaxDynamicSharedMemorySize, DSM);
        cudaFuncSetAttribute(gemm_fp8<256, 1>,  cudaFuncAttributeMaxDynamicSharedMemorySize, DSM);
        cudaFuncSetAttribute(gemm_fp8<256, 2>,  cudaFuncAttributeMaxDynamicSharedMemorySize, DSM);
        cudaFuncSetAttribute(gemm_fp8<256, 3>,  cudaFuncAttributeMaxDynamicSharedMemorySize, DSM);
        attr_done = true;
    }

    // launch indices 0-3: weight composition; 4: LN; 5: GEMM1 (ncu -s 5 profiles this)
    prepA1<<<513, 256>>>(Wv, Wo, W1, dww, b1, dwb);
    prepA2<<<770, 256>>>(Wd, Wg, bd, bg, Wu, Wld, bu);
    prepB1<<<257, 256>>>(W2, b2, bv, Wo, bo);
    prepB2<<<1024, 256>>>(Wu, Wlu, bu);
    ln_kernel<<<BROWS, 256>>>(x, ln_g, ln_b);

    gemm_fp8<1024, 0><<<dim3(4, 256), 256, DSM>>>(
        (const uint8_t*)p_t, (const uint8_t*)p_Wdg,
        (const float*)p_bdg, nullptr, (uint8_t*)p_h, nullptr);
    gemm_fp8<256, 1><<<dim3(2, 256), 256, DSM>>>(
        (const uint8_t*)p_h, (const uint8_t*)p_W1,
        (const float*)p_b1, nullptr, (uint8_t*)p_g, nullptr);
    gemm_fp8<256, 2><<<dim3(2, 256), 256, DSM>>>(
        (const uint8_t*)p_g, (const uint8_t*)p_W2,
        (const float*)p_b2, nullptr, (uint8_t*)p_m, nullptr);
    gemm_fp8<256, 3><<<dim3(8, 256), 256, DSM>>>(
        (const uint8_t*)p_m, (const uint8_t*)p_Wu,
        (const float*)p_bu, x, nullptr, out);
}